// round 12
// baseline (speedup 1.0000x reference)
#include <cuda_runtime.h>
#include <cuda_fp16.h>
#include <stdint.h>

#define NROWS 16384
#define KSPLIT 16
#define TILES (128 * KSPLIT)     // 2048
#define CHUNK (NROWS / KSPLIT)   // 1024 keys per chunk
#define NIT   (CHUNK / 64)       // 16 inner iterations
#define GRID_ATTN 296            // 148 SMs x occupancy 2

// ---------------- scratch (device globals; no allocation allowed) ----------------
__device__ float  g_X  [NROWS * 128];          // layer output / next-layer input
__device__ __half g_G  [NROWS * 64];           // graph-learn projection (fp16)
__device__ float  g_SQ [NROWS];                // |g16|^2
__device__ __half g_H  [NROWS * 128];          // gnn projection (fp16)
__device__ __half g_HR [NROWS * 128];          // fp32-fp16 residual of H
__device__ float  g_PO [(size_t)KSPLIT * NROWS * 128];  // partial O per keychunk
__device__ float  g_PRS[(size_t)KSPLIT * NROWS];        // partial rowsums

// ---------------- asm helpers ----------------
__device__ __forceinline__ void mma_16816(float (&c)[4], const uint32_t (&a)[4],
                                          uint32_t b0, uint32_t b1) {
    asm volatile(
        "mma.sync.aligned.m16n8k16.row.col.f32.f16.f16.f32 "
        "{%0,%1,%2,%3},{%4,%5,%6,%7},{%8,%9},{%0,%1,%2,%3};\n"
        : "+f"(c[0]), "+f"(c[1]), "+f"(c[2]), "+f"(c[3])
        : "r"(a[0]), "r"(a[1]), "r"(a[2]), "r"(a[3]), "r"(b0), "r"(b1));
}
__device__ __forceinline__ void ldsm4(uint32_t &r0, uint32_t &r1, uint32_t &r2, uint32_t &r3,
                                      uint32_t addr) {
    asm volatile("ldmatrix.sync.aligned.m8n8.x4.shared.b16 {%0,%1,%2,%3},[%4];\n"
                 : "=r"(r0), "=r"(r1), "=r"(r2), "=r"(r3) : "r"(addr));
}
__device__ __forceinline__ void ldsm4t(uint32_t &r0, uint32_t &r1, uint32_t &r2, uint32_t &r3,
                                       uint32_t addr) {
    asm volatile("ldmatrix.sync.aligned.m8n8.x4.trans.shared.b16 {%0,%1,%2,%3},[%4];\n"
                 : "=r"(r0), "=r"(r1), "=r"(r2), "=r"(r3) : "r"(addr));
}
__device__ __forceinline__ void cp16(uint32_t dst, const void* src) {
    asm volatile("cp.async.cg.shared.global [%0], [%1], 16;\n" :: "r"(dst), "l"(src));
}
#define CP_COMMIT() asm volatile("cp.async.commit_group;\n" ::: "memory")
#define CP_WAIT1()  asm volatile("cp.async.wait_group 1;\n" ::: "memory")

// ---------------- projection kernels ----------------
// X[N,128] @ W[128,DOUT] + B.  GMODE: relu -> fp16 G + |g16|^2.
// !GMODE: fp16 H + fp16 residual (h32 - h16).
template<int DOUT, bool GMODE>
__global__ __launch_bounds__(256) void proj_kernel(
    const float* __restrict__ X, const float* __restrict__ W, const float* __restrict__ B,
    __half* __restrict__ outh, __half* __restrict__ outres, float* __restrict__ sq)
{
    constexpr int CS = DOUT / 32;
    __shared__ __align__(16) float Xs[32 * 132];
    __shared__ __align__(16) float Ws[32 * DOUT];

    const int tid  = threadIdx.x;
    const int lane = tid & 31;
    const int wy   = tid >> 5;
    const int rowbase = blockIdx.x * 32;

    #pragma unroll
    for (int i = tid; i < 32 * 32; i += 256) {
        int r = i >> 5, c = i & 31;
        ((float4*)(Xs + r * 132))[c] =
            ((const float4*)(X + (size_t)(rowbase + r) * 128))[c];
    }

    float acc[4][CS];
    #pragma unroll
    for (int rs = 0; rs < 4; rs++)
        #pragma unroll
        for (int cs = 0; cs < CS; cs++) acc[rs][cs] = 0.f;

    for (int kc = 0; kc < 128; kc += 32) {
        __syncthreads();
        #pragma unroll
        for (int i = tid; i < 32 * DOUT / 4; i += 256)
            ((float4*)Ws)[i] = ((const float4*)(W + (size_t)kc * DOUT))[i];
        __syncthreads();

        #pragma unroll
        for (int k4 = 0; k4 < 8; k4++) {
            float4 xv[4];
            #pragma unroll
            for (int rs = 0; rs < 4; rs++)
                xv[rs] = *(const float4*)(Xs + (wy + rs * 8) * 132 + kc + k4 * 4);
            #pragma unroll
            for (int kk = 0; kk < 4; kk++) {
                float wv[CS];
                if (CS == 4) {
                    float4 w4 = *(const float4*)(Ws + (k4 * 4 + kk) * DOUT + lane * 4);
                    wv[0] = w4.x; wv[1] = w4.y; wv[2] = w4.z; wv[3 % CS] = w4.w;
                } else {
                    float2 w2 = *(const float2*)(Ws + (k4 * 4 + kk) * DOUT + lane * 2);
                    wv[0] = w2.x; wv[1 % CS] = w2.y;
                }
                #pragma unroll
                for (int rs = 0; rs < 4; rs++) {
                    float xk = ((const float*)&xv[rs])[kk];
                    #pragma unroll
                    for (int cs = 0; cs < CS; cs++)
                        acc[rs][cs] = fmaf(xk, wv[cs], acc[rs][cs]);
                }
            }
        }
    }

    #pragma unroll
    for (int rs = 0; rs < 4; rs++) {
        int row = rowbase + wy + rs * 8;
        float ssq = 0.f;
        #pragma unroll
        for (int cs = 0; cs < CS; cs++) {
            int col = lane * CS + cs;
            float v = acc[rs][cs] + B[col];
            if (GMODE) v = fmaxf(v, 0.f);
            __half h = __float2half_rn(v);
            outh[(size_t)row * DOUT + col] = h;
            float vh = __half2float(h);
            if (GMODE) ssq += vh * vh;
            else       outres[(size_t)row * DOUT + col] = __float2half_rn(v - vh);
        }
        if (GMODE) {
            #pragma unroll
            for (int off = 16; off; off >>= 1) ssq += __shfl_xor_sync(0xffffffffu, ssq, off);
            if (lane == 0) sq[row] = ssq;
        }
    }
}

// ---------------- fused sigmoid-attention kernel (persistent, key-split) ----------------
// partialO[kc] += sigmoid(t*(2 g_i.g_j - sq_i - sq_j) + th) @ h ; partialRS[kc] += rowsum
// sigmoid: u = e^x (fp32 EX2); tail fast-path p = u - u^2 when the whole warp has
// u < 0.004 (rel err < 1.6e-5); else exact u/(1+u). Argument stays fp32 (R7 lesson).
// 3-stage cp.async pipeline, ONE barrier per iter. 296 persistent CTAs (2/SM).

// dynamic smem (bytes): 3 stages of {K 64x72 f16, H 64x136 f16, SQ 64 f32}
#define OFF_K(b)   ((b) * 9216)
#define OFF_H(b)   (27648 + (b) * 17408)
#define OFF_SQ(b)  (79872 + (b) * 256)
#define SMEM_BYTES 80640

__global__ __launch_bounds__(256, 2) void attn_kernel(
    const __half* __restrict__ G, const float* __restrict__ SQ,
    const __half* __restrict__ H,
    const float* __restrict__ tempp, const float* __restrict__ thetap,
    float* __restrict__ PO, float* __restrict__ PRS)
{
    extern __shared__ __align__(16) char dsm[];
    const uint32_t smem_u32 = (uint32_t)__cvta_generic_to_shared(dsm);

    const int tid  = threadIdx.x;
    const int lane = tid & 31;
    const int warp = tid >> 5;
    const int gid  = lane >> 2;
    const int qid  = lane & 3;

    const float tt = 1.0f + *tempp;       // t
    const float th = 5.0f + *thetap;
    const float t2 = 2.0f * tt;
    const uint32_t ONES = 0x3C003C00u;

    const uint32_t* G32 = reinterpret_cast<const uint32_t*>(G);

    for (int t = blockIdx.x; t < TILES; t += GRID_ATTN) {
        const int rb = t & 127;
        const int kc = t >> 7;
        const int keybase = kc * CHUNK;
        const int rowbase = rb * 128 + warp * 16;
        const int r0 = rowbase + gid, r1 = r0 + 8;

        // Q fragments
        uint32_t aq[4][4];
        #pragma unroll
        for (int ks = 0; ks < 4; ks++) {
            int c0 = ks * 8 + qid;
            aq[ks][0] = G32[(size_t)r0 * 32 + c0];
            aq[ks][1] = G32[(size_t)r1 * 32 + c0];
            aq[ks][2] = G32[(size_t)r0 * 32 + c0 + 4];
            aq[ks][3] = G32[(size_t)r1 * 32 + c0 + 4];
        }
        const float ci0 = fmaf(-tt, SQ[r0], th);   // th - t*sq_i
        const float ci1 = fmaf(-tt, SQ[r1], th);

        float accO[16][4];
        #pragma unroll
        for (int i = 0; i < 16; i++)
            #pragma unroll
            for (int j = 0; j < 4; j++) accO[i][j] = 0.f;
        float rsacc[4] = {0.f, 0.f, 0.f, 0.f};

        // ---- async tile loader (stage b = it % 3) ----
        auto issue = [&](int it2) {
            if (it2 < NIT) {
                const int b = it2 % 3;
                const int j0 = keybase + it2 * 64;
                uint32_t kdst = smem_u32 + OFF_K(b);
                const char* ksrc = (const char*)(G + (size_t)j0 * 64);
                #pragma unroll
                for (int i = tid; i < 512; i += 256) {
                    int r = i >> 3, c = i & 7;
                    cp16(kdst + (r * 72 + c * 8) * 2, ksrc + i * 16);
                }
                uint32_t hdst = smem_u32 + OFF_H(b);
                const char* hsrc = (const char*)(H + (size_t)j0 * 128);
                #pragma unroll
                for (int i = tid; i < 1024; i += 256) {
                    int r = i >> 4, c = i & 15;
                    cp16(hdst + (r * 136 + c * 8) * 2, hsrc + i * 16);
                }
                if (tid < 16)
                    cp16(smem_u32 + OFF_SQ(b) + tid * 16, (const char*)(SQ + j0) + tid * 16);
            }
        };

        issue(0); CP_COMMIT();
        issue(1); CP_COMMIT();

        for (int it = 0; it < NIT; it++) {
            const int b = it % 3;

            CP_WAIT1();          // tile(it) resident (pending: it, it+1 before this)
            __syncthreads();     // all warps done with compute(it-1) -> buf (it-1)%3 reusable
            issue(it + 2);       // writes buf (it+2)%3 == (it-1)%3 : safe after barrier
            CP_COMMIT();

            const uint32_t skb = smem_u32 + OFF_K(b);
            const uint32_t shb = smem_u32 + OFF_H(b);
            const float* sqb = (const float*)(dsm + OFF_SQ(b));

            // ---- S = Gq @ Gk^T -> P = sigmoid (fp32 arg) -> fp16 pack ----
            uint32_t pP[8][2];
            #pragma unroll
            for (int nb = 0; nb < 8; nb++) {
                float c4[4] = {0.f, 0.f, 0.f, 0.f};
                uint32_t b0, b1, b2, b3, b4, b5, b6, b7;
                uint32_t addr = skb + ((nb * 8 + (lane & 7)) * 72 + (lane >> 3) * 8) * 2;
                ldsm4(b0, b1, b2, b3, addr);
                ldsm4(b4, b5, b6, b7, addr + 64);
                mma_16816(c4, aq[0], b0, b1);
                mma_16816(c4, aq[1], b2, b3);
                mma_16816(c4, aq[2], b4, b5);
                mma_16816(c4, aq[3], b6, b7);

                float tsq0 = tt * sqb[nb * 8 + qid * 2];
                float tsq1 = tt * sqb[nb * 8 + qid * 2 + 1];
                float u00 = __expf(fmaf(t2, c4[0], ci0 - tsq0));
                float u01 = __expf(fmaf(t2, c4[1], ci0 - tsq1));
                float u10 = __expf(fmaf(t2, c4[2], ci1 - tsq0));
                float u11 = __expf(fmaf(t2, c4[3], ci1 - tsq1));

                float p00, p01, p10, p11;
                float umax = fmaxf(fmaxf(u00, u01), fmaxf(u10, u11));
                if (__any_sync(0xffffffffu, umax > 0.004f)) {
                    p00 = __fdividef(u00, 1.0f + u00);
                    p01 = __fdividef(u01, 1.0f + u01);
                    p10 = __fdividef(u10, 1.0f + u10);
                    p11 = __fdividef(u11, 1.0f + u11);
                } else {
                    // u/(1+u) = u - u^2 + O(u^3); rel err <= u^2 < 1.6e-5
                    p00 = fmaf(-u00, u00, u00);
                    p01 = fmaf(-u01, u01, u01);
                    p10 = fmaf(-u10, u10, u10);
                    p11 = fmaf(-u11, u11, u11);
                }

                __half2 ph0 = __floats2half2_rn(p00, p01);
                __half2 ph1 = __floats2half2_rn(p10, p11);
                pP[nb][0] = *reinterpret_cast<uint32_t*>(&ph0);
                pP[nb][1] = *reinterpret_cast<uint32_t*>(&ph1);
            }

            // ---- O += P @ H ; rowsum += P @ 1 (same fp16 P, fp32 accum) ----
            #pragma unroll
            for (int ks = 0; ks < 4; ks++) {
                uint32_t ap[4] = { pP[2*ks][0], pP[2*ks][1], pP[2*ks+1][0], pP[2*ks+1][1] };
                mma_16816(rsacc, ap, ONES, ONES);
                #pragma unroll
                for (int np = 0; np < 8; np++) {
                    uint32_t h0, h1, h2, h3;
                    uint32_t addr = shb +
                        ((ks * 16 + ((lane >> 3) & 1) * 8 + (lane & 7)) * 136 +
                         np * 16 + (lane >> 4) * 8) * 2;
                    ldsm4t(h0, h1, h2, h3, addr);
                    mma_16816(accO[2 * np],     ap, h0, h1);
                    mma_16816(accO[2 * np + 1], ap, h2, h3);
                }
            }
        }

        // ---- store partial O and rowsums ----
        float* po = PO + (size_t)kc * NROWS * 128;
        #pragma unroll
        for (int nb = 0; nb < 16; nb++) {
            int c0 = nb * 8 + qid * 2;
            *(float2*)(po + (size_t)r0 * 128 + c0) = make_float2(accO[nb][0], accO[nb][1]);
            *(float2*)(po + (size_t)r1 * 128 + c0) = make_float2(accO[nb][2], accO[nb][3]);
        }
        if (qid == 0) {
            PRS[(size_t)kc * NROWS + r0] = rsacc[0];
            PRS[(size_t)kc * NROWS + r1] = rsacc[2];
        }
        __syncthreads();   // keep smem stages quiescent before next tile's prologue issues
    }
}

// ---------------- combine: sum partials, diag residual, normalize, relu ----------------
__global__ __launch_bounds__(256) void combine_kernel(
    const float* __restrict__ PO, const float* __restrict__ PRS,
    const __half* __restrict__ HR, const float* __restrict__ thetap,
    float* __restrict__ X, int do_relu)
{
    const int row = blockIdx.x * 2 + (threadIdx.x >> 7);
    const int col = threadIdx.x & 127;
    const float th = 5.0f + *thetap;
    const float pd = 1.0f / (1.0f + expf(-th));

    float acc = 0.f, rs = 0.f;
    #pragma unroll
    for (int k = 0; k < KSPLIT; k++) {
        acc += PO[((size_t)k * NROWS + row) * 128 + col];
        rs  += PRS[(size_t)k * NROWS + row];
    }
    float hr = __half2float(HR[(size_t)row * 128 + col]);
    float v = fmaf(pd, hr, acc) / rs;
    if (do_relu) v = fmaxf(v, 0.f);
    X[(size_t)row * 128 + col] = v;
}

// ---------------- final projection (128->10) + softmax ----------------
__global__ __launch_bounds__(256) void out_kernel(
    const float* __restrict__ X, const float* __restrict__ W,
    const float* __restrict__ B, float* __restrict__ out)
{
    int gw = (blockIdx.x * blockDim.x + threadIdx.x) >> 5;
    int lane = threadIdx.x & 31;
    if (gw >= NROWS) return;
    const float* x = X + (size_t)gw * 128;
    float xv0 = x[lane], xv1 = x[lane + 32], xv2 = x[lane + 64], xv3 = x[lane + 96];
    float lg[10];
    #pragma unroll
    for (int c = 0; c < 10; c++) {
        float s = xv0 * W[lane * 10 + c] + xv1 * W[(lane + 32) * 10 + c]
                + xv2 * W[(lane + 64) * 10 + c] + xv3 * W[(lane + 96) * 10 + c];
        #pragma unroll
        for (int off = 16; off; off >>= 1) s += __shfl_xor_sync(0xffffffffu, s, off);
        lg[c] = s + B[c];
    }
    if (lane == 0) {
        float mx = lg[0];
        #pragma unroll
        for (int c = 1; c < 10; c++) mx = fmaxf(mx, lg[c]);
        float den = 0.f, e[10];
        #pragma unroll
        for (int c = 0; c < 10; c++) { e[c] = expf(lg[c] - mx); den += e[c]; }
        float inv = 1.0f / den;
        #pragma unroll
        for (int c = 0; c < 10; c++) out[(size_t)gw * 10 + c] = e[c] * inv;
    }
}

// ---------------- launch ----------------
extern "C" void kernel_launch(void* const* d_in, const int* in_sizes, int n_in,
                              void* d_out, int out_size)
{
    const float* feat   = (const float*)d_in[0];
    const float* gl_w0  = (const float*)d_in[1];
    const float* gl_b0  = (const float*)d_in[2];
    const float* gl_w1  = (const float*)d_in[3];
    const float* gl_b1  = (const float*)d_in[4];
    const float* gnn_w0 = (const float*)d_in[5];
    const float* gnn_b0 = (const float*)d_in[6];
    const float* gnn_w1 = (const float*)d_in[7];
    const float* gnn_b1 = (const float*)d_in[8];
    const float* out_w  = (const float*)d_in[9];
    const float* out_b  = (const float*)d_in[10];
    const float* temp   = (const float*)d_in[11];
    const float* theta  = (const float*)d_in[12];

    float*  Xp;  cudaGetSymbolAddress((void**)&Xp,  g_X);
    __half* Gp;  cudaGetSymbolAddress((void**)&Gp,  g_G);
    float*  SQp; cudaGetSymbolAddress((void**)&SQp, g_SQ);
    __half* Hp;  cudaGetSymbolAddress((void**)&Hp,  g_H);
    __half* HRp; cudaGetSymbolAddress((void**)&HRp, g_HR);
    float*  POp; cudaGetSymbolAddress((void**)&POp, g_PO);
    float*  PRSp;cudaGetSymbolAddress((void**)&PRSp,g_PRS);

    static bool attr_set = false;
    if (!attr_set) {
        cudaFuncSetAttribute(attn_kernel, cudaFuncAttributeMaxDynamicSharedMemorySize,
                             SMEM_BYTES);
        attr_set = true;
    }

    // layer 1
    proj_kernel<64,  true ><<<NROWS / 32, 256>>>(feat, gl_w0,  gl_b0,  Gp, nullptr, SQp);
    proj_kernel<128, false><<<NROWS / 32, 256>>>(feat, gnn_w0, gnn_b0, Hp, HRp, nullptr);
    attn_kernel<<<GRID_ATTN, 256, SMEM_BYTES>>>(Gp, SQp, Hp, temp, theta, POp, PRSp);
    combine_kernel<<<NROWS / 2, 256>>>(POp, PRSp, HRp, theta, Xp, 1);

    // layer 2
    proj_kernel<64,  true ><<<NROWS / 32, 256>>>(Xp, gl_w1,  gl_b1,  Gp, nullptr, SQp);
    proj_kernel<128, false><<<NROWS / 32, 256>>>(Xp, gnn_w1, gnn_b1, Hp, HRp, nullptr);
    attn_kernel<<<GRID_ATTN, 256, SMEM_BYTES>>>(Gp, SQp, Hp, temp, theta, POp, PRSp);
    combine_kernel<<<NROWS / 2, 256>>>(POp, PRSp, HRp, theta, Xp, 0);

    // output head + softmax
    out_kernel<<<NROWS * 32 / 256, 256>>>(Xp, out_w, out_b, (float*)d_out);
}

// round 13
// speedup vs baseline: 1.2627x; 1.2627x over previous
#include <cuda_runtime.h>
#include <cuda_fp16.h>
#include <stdint.h>

#define NROWS 16384
#define KSPLIT 8
#define TILES (128 * KSPLIT)     // 1024
#define CHUNK (NROWS / KSPLIT)   // 2048 keys per chunk
#define NIT   (CHUNK / 64)       // 32 inner iterations
#define GRID_ATTN 148

// ---------------- scratch (device globals; no allocation allowed) ----------------
__device__ float  g_X  [NROWS * 128];          // layer output / next-layer input
__device__ __half g_G  [NROWS * 64];           // graph-learn projection (fp16)
__device__ float  g_SQ [NROWS];                // |g16|^2
__device__ __half g_H  [NROWS * 128];          // gnn projection (fp16)
__device__ __half g_HR [NROWS * 128];          // fp32-fp16 residual of H
__device__ float  g_PO [(size_t)KSPLIT * NROWS * 128];  // partial O per keychunk
__device__ float  g_PRS[(size_t)KSPLIT * NROWS];        // partial rowsums

// ---------------- asm helpers ----------------
__device__ __forceinline__ void mma_16816(float (&c)[4], const uint32_t (&a)[4],
                                          uint32_t b0, uint32_t b1) {
    asm volatile(
        "mma.sync.aligned.m16n8k16.row.col.f32.f16.f16.f32 "
        "{%0,%1,%2,%3},{%4,%5,%6,%7},{%8,%9},{%0,%1,%2,%3};\n"
        : "+f"(c[0]), "+f"(c[1]), "+f"(c[2]), "+f"(c[3])
        : "r"(a[0]), "r"(a[1]), "r"(a[2]), "r"(a[3]), "r"(b0), "r"(b1));
}
__device__ __forceinline__ void ldsm4(uint32_t &r0, uint32_t &r1, uint32_t &r2, uint32_t &r3,
                                      uint32_t addr) {
    asm volatile("ldmatrix.sync.aligned.m8n8.x4.shared.b16 {%0,%1,%2,%3},[%4];\n"
                 : "=r"(r0), "=r"(r1), "=r"(r2), "=r"(r3) : "r"(addr));
}
__device__ __forceinline__ void ldsm4t(uint32_t &r0, uint32_t &r1, uint32_t &r2, uint32_t &r3,
                                       uint32_t addr) {
    asm volatile("ldmatrix.sync.aligned.m8n8.x4.trans.shared.b16 {%0,%1,%2,%3},[%4];\n"
                 : "=r"(r0), "=r"(r1), "=r"(r2), "=r"(r3) : "r"(addr));
}
__device__ __forceinline__ void cp16(uint32_t dst, const void* src) {
    asm volatile("cp.async.cg.shared.global [%0], [%1], 16;\n" :: "r"(dst), "l"(src));
}
#define CP_COMMIT() asm volatile("cp.async.commit_group;\n" ::: "memory")
#define CP_WAIT1()  asm volatile("cp.async.wait_group 1;\n" ::: "memory")

// ---------------- projection kernels ----------------
// X[N,128] @ W[128,DOUT] + B.  GMODE: relu -> fp16 G + |g16|^2.
// !GMODE: fp16 H + fp16 residual (h32 - h16).
template<int DOUT, bool GMODE>
__global__ __launch_bounds__(256) void proj_kernel(
    const float* __restrict__ X, const float* __restrict__ W, const float* __restrict__ B,
    __half* __restrict__ outh, __half* __restrict__ outres, float* __restrict__ sq)
{
    constexpr int CS = DOUT / 32;
    __shared__ __align__(16) float Xs[32 * 132];
    __shared__ __align__(16) float Ws[32 * DOUT];

    const int tid  = threadIdx.x;
    const int lane = tid & 31;
    const int wy   = tid >> 5;
    const int rowbase = blockIdx.x * 32;

    #pragma unroll
    for (int i = tid; i < 32 * 32; i += 256) {
        int r = i >> 5, c = i & 31;
        ((float4*)(Xs + r * 132))[c] =
            ((const float4*)(X + (size_t)(rowbase + r) * 128))[c];
    }

    float acc[4][CS];
    #pragma unroll
    for (int rs = 0; rs < 4; rs++)
        #pragma unroll
        for (int cs = 0; cs < CS; cs++) acc[rs][cs] = 0.f;

    for (int kc = 0; kc < 128; kc += 32) {
        __syncthreads();
        #pragma unroll
        for (int i = tid; i < 32 * DOUT / 4; i += 256)
            ((float4*)Ws)[i] = ((const float4*)(W + (size_t)kc * DOUT))[i];
        __syncthreads();

        #pragma unroll
        for (int k4 = 0; k4 < 8; k4++) {
            float4 xv[4];
            #pragma unroll
            for (int rs = 0; rs < 4; rs++)
                xv[rs] = *(const float4*)(Xs + (wy + rs * 8) * 132 + kc + k4 * 4);
            #pragma unroll
            for (int kk = 0; kk < 4; kk++) {
                float wv[CS];
                if (CS == 4) {
                    float4 w4 = *(const float4*)(Ws + (k4 * 4 + kk) * DOUT + lane * 4);
                    wv[0] = w4.x; wv[1] = w4.y; wv[2] = w4.z; wv[3 % CS] = w4.w;
                } else {
                    float2 w2 = *(const float2*)(Ws + (k4 * 4 + kk) * DOUT + lane * 2);
                    wv[0] = w2.x; wv[1 % CS] = w2.y;
                }
                #pragma unroll
                for (int rs = 0; rs < 4; rs++) {
                    float xk = ((const float*)&xv[rs])[kk];
                    #pragma unroll
                    for (int cs = 0; cs < CS; cs++)
                        acc[rs][cs] = fmaf(xk, wv[cs], acc[rs][cs]);
                }
            }
        }
    }

    #pragma unroll
    for (int rs = 0; rs < 4; rs++) {
        int row = rowbase + wy + rs * 8;
        float ssq = 0.f;
        #pragma unroll
        for (int cs = 0; cs < CS; cs++) {
            int col = lane * CS + cs;
            float v = acc[rs][cs] + B[col];
            if (GMODE) v = fmaxf(v, 0.f);
            __half h = __float2half_rn(v);
            outh[(size_t)row * DOUT + col] = h;
            float vh = __half2float(h);
            if (GMODE) ssq += vh * vh;
            else       outres[(size_t)row * DOUT + col] = __float2half_rn(v - vh);
        }
        if (GMODE) {
            #pragma unroll
            for (int off = 16; off; off >>= 1) ssq += __shfl_xor_sync(0xffffffffu, ssq, off);
            if (lane == 0) sq[row] = ssq;
        }
    }
}

// ---------------- fused sigmoid-attention kernel (persistent, key-split) ----------------
// partialO[kc] += sigmoid(t*(2 g_i.g_j - sq_i - sq_j) + th) @ h ; partialRS[kc] += rowsum
// sigmoid: u = e^x (fp32 EX2); warp-uniform tail fast-path p = u - u^2 when all lanes
// have u < 0.004 (rel err < 1.6e-5); else exact u/(1+u). Argument stays fp32 (R7 lesson).
// 3-stage cp.async pipeline, ONE barrier per iter. Occupancy 1 (R12 lesson: occ-2
// register cap spills the 64-reg O accumulator -> 1.8x regression).

// dynamic smem (bytes): 3 stages of {K 64x72 f16, H 64x136 f16, SQ 64 f32}
#define OFF_K(b)   ((b) * 9216)
#define OFF_H(b)   (27648 + (b) * 17408)
#define OFF_SQ(b)  (79872 + (b) * 256)
#define SMEM_BYTES 80640

__global__ __launch_bounds__(256, 1) void attn_kernel(
    const __half* __restrict__ G, const float* __restrict__ SQ,
    const __half* __restrict__ H,
    const float* __restrict__ tempp, const float* __restrict__ thetap,
    float* __restrict__ PO, float* __restrict__ PRS)
{
    extern __shared__ __align__(16) char dsm[];
    const uint32_t smem_u32 = (uint32_t)__cvta_generic_to_shared(dsm);

    const int tid  = threadIdx.x;
    const int lane = tid & 31;
    const int warp = tid >> 5;
    const int gid  = lane >> 2;
    const int qid  = lane & 3;

    const float tt = 1.0f + *tempp;       // t
    const float th = 5.0f + *thetap;
    const float t2 = 2.0f * tt;
    const uint32_t ONES = 0x3C003C00u;

    const uint32_t* G32 = reinterpret_cast<const uint32_t*>(G);

    for (int t = blockIdx.x; t < TILES; t += GRID_ATTN) {
        const int rb = t & 127;
        const int kc = t >> 7;
        const int keybase = kc * CHUNK;
        const int rowbase = rb * 128 + warp * 16;
        const int r0 = rowbase + gid, r1 = r0 + 8;

        // Q fragments
        uint32_t aq[4][4];
        #pragma unroll
        for (int ks = 0; ks < 4; ks++) {
            int c0 = ks * 8 + qid;
            aq[ks][0] = G32[(size_t)r0 * 32 + c0];
            aq[ks][1] = G32[(size_t)r1 * 32 + c0];
            aq[ks][2] = G32[(size_t)r0 * 32 + c0 + 4];
            aq[ks][3] = G32[(size_t)r1 * 32 + c0 + 4];
        }
        const float ci0 = fmaf(-tt, SQ[r0], th);   // th - t*sq_i
        const float ci1 = fmaf(-tt, SQ[r1], th);

        float accO[16][4];
        #pragma unroll
        for (int i = 0; i < 16; i++)
            #pragma unroll
            for (int j = 0; j < 4; j++) accO[i][j] = 0.f;
        float rsacc[4] = {0.f, 0.f, 0.f, 0.f};

        // ---- async tile loader (stage b = it % 3) ----
        auto issue = [&](int it2) {
            if (it2 < NIT) {
                const int b = it2 % 3;
                const int j0 = keybase + it2 * 64;
                uint32_t kdst = smem_u32 + OFF_K(b);
                const char* ksrc = (const char*)(G + (size_t)j0 * 64);
                #pragma unroll
                for (int i = tid; i < 512; i += 256) {
                    int r = i >> 3, c = i & 7;
                    cp16(kdst + (r * 72 + c * 8) * 2, ksrc + i * 16);
                }
                uint32_t hdst = smem_u32 + OFF_H(b);
                const char* hsrc = (const char*)(H + (size_t)j0 * 128);
                #pragma unroll
                for (int i = tid; i < 1024; i += 256) {
                    int r = i >> 4, c = i & 15;
                    cp16(hdst + (r * 136 + c * 8) * 2, hsrc + i * 16);
                }
                if (tid < 16)
                    cp16(smem_u32 + OFF_SQ(b) + tid * 16, (const char*)(SQ + j0) + tid * 16);
            }
        };

        issue(0); CP_COMMIT();
        issue(1); CP_COMMIT();

        for (int it = 0; it < NIT; it++) {
            const int b = it % 3;

            CP_WAIT1();          // tile(it) resident (pending groups were: it, it+1)
            __syncthreads();     // all warps done with compute(it-1) -> buf (it-1)%3 reusable
            issue(it + 2);       // writes buf (it+2)%3 == (it-1)%3 : safe after barrier
            CP_COMMIT();

            const uint32_t skb = smem_u32 + OFF_K(b);
            const uint32_t shb = smem_u32 + OFF_H(b);
            const float* sqb = (const float*)(dsm + OFF_SQ(b));

            // ---- S = Gq @ Gk^T -> P = sigmoid (fp32 arg) -> fp16 pack ----
            uint32_t pP[8][2];
            #pragma unroll
            for (int nb = 0; nb < 8; nb++) {
                float c4[4] = {0.f, 0.f, 0.f, 0.f};
                uint32_t b0, b1, b2, b3, b4, b5, b6, b7;
                uint32_t addr = skb + ((nb * 8 + (lane & 7)) * 72 + (lane >> 3) * 8) * 2;
                ldsm4(b0, b1, b2, b3, addr);
                ldsm4(b4, b5, b6, b7, addr + 64);
                mma_16816(c4, aq[0], b0, b1);
                mma_16816(c4, aq[1], b2, b3);
                mma_16816(c4, aq[2], b4, b5);
                mma_16816(c4, aq[3], b6, b7);

                float tsq0 = tt * sqb[nb * 8 + qid * 2];
                float tsq1 = tt * sqb[nb * 8 + qid * 2 + 1];
                float u00 = __expf(fmaf(t2, c4[0], ci0 - tsq0));
                float u01 = __expf(fmaf(t2, c4[1], ci0 - tsq1));
                float u10 = __expf(fmaf(t2, c4[2], ci1 - tsq0));
                float u11 = __expf(fmaf(t2, c4[3], ci1 - tsq1));

                float p00, p01, p10, p11;
                float umax = fmaxf(fmaxf(u00, u01), fmaxf(u10, u11));
                if (__any_sync(0xffffffffu, umax > 0.004f)) {
                    p00 = __fdividef(u00, 1.0f + u00);
                    p01 = __fdividef(u01, 1.0f + u01);
                    p10 = __fdividef(u10, 1.0f + u10);
                    p11 = __fdividef(u11, 1.0f + u11);
                } else {
                    // u/(1+u) = u - u^2 + O(u^3); rel err <= u^2 < 1.6e-5
                    p00 = fmaf(-u00, u00, u00);
                    p01 = fmaf(-u01, u01, u01);
                    p10 = fmaf(-u10, u10, u10);
                    p11 = fmaf(-u11, u11, u11);
                }

                __half2 ph0 = __floats2half2_rn(p00, p01);
                __half2 ph1 = __floats2half2_rn(p10, p11);
                pP[nb][0] = *reinterpret_cast<uint32_t*>(&ph0);
                pP[nb][1] = *reinterpret_cast<uint32_t*>(&ph1);
            }

            // ---- O += P @ H ; rowsum += P @ 1 (same fp16 P, fp32 accum) ----
            #pragma unroll
            for (int ks = 0; ks < 4; ks++) {
                uint32_t ap[4] = { pP[2*ks][0], pP[2*ks][1], pP[2*ks+1][0], pP[2*ks+1][1] };
                mma_16816(rsacc, ap, ONES, ONES);
                #pragma unroll
                for (int np = 0; np < 8; np++) {
                    uint32_t h0, h1, h2, h3;
                    uint32_t addr = shb +
                        ((ks * 16 + ((lane >> 3) & 1) * 8 + (lane & 7)) * 136 +
                         np * 16 + (lane >> 4) * 8) * 2;
                    ldsm4t(h0, h1, h2, h3, addr);
                    mma_16816(accO[2 * np],     ap, h0, h1);
                    mma_16816(accO[2 * np + 1], ap, h2, h3);
                }
            }
        }

        // ---- store partial O and rowsums ----
        float* po = PO + (size_t)kc * NROWS * 128;
        #pragma unroll
        for (int nb = 0; nb < 16; nb++) {
            int c0 = nb * 8 + qid * 2;
            *(float2*)(po + (size_t)r0 * 128 + c0) = make_float2(accO[nb][0], accO[nb][1]);
            *(float2*)(po + (size_t)r1 * 128 + c0) = make_float2(accO[nb][2], accO[nb][3]);
        }
        if (qid == 0) {
            PRS[(size_t)kc * NROWS + r0] = rsacc[0];
            PRS[(size_t)kc * NROWS + r1] = rsacc[2];
        }
        __syncthreads();   // protect stage buffers from next tile's prologue issues
    }
}

// ---------------- combine: sum partials, diag residual, normalize, relu ----------------
__global__ __launch_bounds__(256) void combine_kernel(
    const float* __restrict__ PO, const float* __restrict__ PRS,
    const __half* __restrict__ HR, const float* __restrict__ thetap,
    float* __restrict__ X, int do_relu)
{
    const int row = blockIdx.x * 2 + (threadIdx.x >> 7);
    const int col = threadIdx.x & 127;
    const float th = 5.0f + *thetap;
    const float pd = 1.0f / (1.0f + expf(-th));

    float acc = 0.f, rs = 0.f;
    #pragma unroll
    for (int k = 0; k < KSPLIT; k++) {
        acc += PO[((size_t)k * NROWS + row) * 128 + col];
        rs  += PRS[(size_t)k * NROWS + row];
    }
    float hr = __half2float(HR[(size_t)row * 128 + col]);
    float v = fmaf(pd, hr, acc) / rs;
    if (do_relu) v = fmaxf(v, 0.f);
    X[(size_t)row * 128 + col] = v;
}

// ---------------- final projection (128->10) + softmax ----------------
__global__ __launch_bounds__(256) void out_kernel(
    const float* __restrict__ X, const float* __restrict__ W,
    const float* __restrict__ B, float* __restrict__ out)
{
    int gw = (blockIdx.x * blockDim.x + threadIdx.x) >> 5;
    int lane = threadIdx.x & 31;
    if (gw >= NROWS) return;
    const float* x = X + (size_t)gw * 128;
    float xv0 = x[lane], xv1 = x[lane + 32], xv2 = x[lane + 64], xv3 = x[lane + 96];
    float lg[10];
    #pragma unroll
    for (int c = 0; c < 10; c++) {
        float s = xv0 * W[lane * 10 + c] + xv1 * W[(lane + 32) * 10 + c]
                + xv2 * W[(lane + 64) * 10 + c] + xv3 * W[(lane + 96) * 10 + c];
        #pragma unroll
        for (int off = 16; off; off >>= 1) s += __shfl_xor_sync(0xffffffffu, s, off);
        lg[c] = s + B[c];
    }
    if (lane == 0) {
        float mx = lg[0];
        #pragma unroll
        for (int c = 1; c < 10; c++) mx = fmaxf(mx, lg[c]);
        float den = 0.f, e[10];
        #pragma unroll
        for (int c = 0; c < 10; c++) { e[c] = expf(lg[c] - mx); den += e[c]; }
        float inv = 1.0f / den;
        #pragma unroll
        for (int c = 0; c < 10; c++) out[(size_t)gw * 10 + c] = e[c] * inv;
    }
}

// ---------------- launch ----------------
extern "C" void kernel_launch(void* const* d_in, const int* in_sizes, int n_in,
                              void* d_out, int out_size)
{
    const float* feat   = (const float*)d_in[0];
    const float* gl_w0  = (const float*)d_in[1];
    const float* gl_b0  = (const float*)d_in[2];
    const float* gl_w1  = (const float*)d_in[3];
    const float* gl_b1  = (const float*)d_in[4];
    const float* gnn_w0 = (const float*)d_in[5];
    const float* gnn_b0 = (const float*)d_in[6];
    const float* gnn_w1 = (const float*)d_in[7];
    const float* gnn_b1 = (const float*)d_in[8];
    const float* out_w  = (const float*)d_in[9];
    const float* out_b  = (const float*)d_in[10];
    const float* temp   = (const float*)d_in[11];
    const float* theta  = (const float*)d_in[12];

    float*  Xp;  cudaGetSymbolAddress((void**)&Xp,  g_X);
    __half* Gp;  cudaGetSymbolAddress((void**)&Gp,  g_G);
    float*  SQp; cudaGetSymbolAddress((void**)&SQp, g_SQ);
    __half* Hp;  cudaGetSymbolAddress((void**)&Hp,  g_H);
    __half* HRp; cudaGetSymbolAddress((void**)&HRp, g_HR);
    float*  POp; cudaGetSymbolAddress((void**)&POp, g_PO);
    float*  PRSp;cudaGetSymbolAddress((void**)&PRSp,g_PRS);

    static bool attr_set = false;
    if (!attr_set) {
        cudaFuncSetAttribute(attn_kernel, cudaFuncAttributeMaxDynamicSharedMemorySize,
                             SMEM_BYTES);
        attr_set = true;
    }

    // layer 1
    proj_kernel<64,  true ><<<NROWS / 32, 256>>>(feat, gl_w0,  gl_b0,  Gp, nullptr, SQp);
    proj_kernel<128, false><<<NROWS / 32, 256>>>(feat, gnn_w0, gnn_b0, Hp, HRp, nullptr);
    attn_kernel<<<GRID_ATTN, 256, SMEM_BYTES>>>(Gp, SQp, Hp, temp, theta, POp, PRSp);
    combine_kernel<<<NROWS / 2, 256>>>(POp, PRSp, HRp, theta, Xp, 1);

    // layer 2
    proj_kernel<64,  true ><<<NROWS / 32, 256>>>(Xp, gl_w1,  gl_b1,  Gp, nullptr, SQp);
    proj_kernel<128, false><<<NROWS / 32, 256>>>(Xp, gnn_w1, gnn_b1, Hp, HRp, nullptr);
    attn_kernel<<<GRID_ATTN, 256, SMEM_BYTES>>>(Gp, SQp, Hp, temp, theta, POp, PRSp);
    combine_kernel<<<NROWS / 2, 256>>>(POp, PRSp, HRp, theta, Xp, 0);

    // output head + softmax
    out_kernel<<<NROWS * 32 / 256, 256>>>(Xp, out_w, out_b, (float*)d_out);
}

// round 14
// speedup vs baseline: 1.9095x; 1.5122x over previous
#include <cuda_runtime.h>
#include <cuda_fp16.h>
#include <stdint.h>

#define NROWS 16384
#define KSPLIT 8
#define TILES (128 * KSPLIT)     // 1024
#define CHUNK (NROWS / KSPLIT)   // 2048 keys per chunk
#define NIT   (CHUNK / 64)       // 32 inner iterations
#define GRID_ATTN 148

// ---------------- scratch (device globals; no allocation allowed) ----------------
__device__ float  g_X  [NROWS * 128];          // layer output / next-layer input
__device__ __half g_G  [NROWS * 64];           // graph-learn projection (fp16)
__device__ float  g_SQ [NROWS];                // |g16|^2
__device__ __half g_H  [NROWS * 128];          // gnn projection (fp16)
__device__ __half g_HR [NROWS * 128];          // fp32-fp16 residual of H
__device__ float  g_PO [(size_t)KSPLIT * NROWS * 128];  // partial O per keychunk
__device__ float  g_PRS[(size_t)KSPLIT * NROWS];        // partial rowsums

// ---------------- asm helpers ----------------
__device__ __forceinline__ void mma_16816(float (&c)[4], const uint32_t (&a)[4],
                                          uint32_t b0, uint32_t b1) {
    asm volatile(
        "mma.sync.aligned.m16n8k16.row.col.f32.f16.f16.f32 "
        "{%0,%1,%2,%3},{%4,%5,%6,%7},{%8,%9},{%0,%1,%2,%3};\n"
        : "+f"(c[0]), "+f"(c[1]), "+f"(c[2]), "+f"(c[3])
        : "r"(a[0]), "r"(a[1]), "r"(a[2]), "r"(a[3]), "r"(b0), "r"(b1));
}
__device__ __forceinline__ void ldsm4(uint32_t &r0, uint32_t &r1, uint32_t &r2, uint32_t &r3,
                                      uint32_t addr) {
    asm volatile("ldmatrix.sync.aligned.m8n8.x4.shared.b16 {%0,%1,%2,%3},[%4];\n"
                 : "=r"(r0), "=r"(r1), "=r"(r2), "=r"(r3) : "r"(addr));
}
__device__ __forceinline__ void ldsm4t(uint32_t &r0, uint32_t &r1, uint32_t &r2, uint32_t &r3,
                                       uint32_t addr) {
    asm volatile("ldmatrix.sync.aligned.m8n8.x4.trans.shared.b16 {%0,%1,%2,%3},[%4];\n"
                 : "=r"(r0), "=r"(r1), "=r"(r2), "=r"(r3) : "r"(addr));
}
__device__ __forceinline__ void cp16(uint32_t dst, const void* src) {
    asm volatile("cp.async.cg.shared.global [%0], [%1], 16;\n" :: "r"(dst), "l"(src));
}
#define CP_COMMIT() asm volatile("cp.async.commit_group;\n" ::: "memory")
#define CP_WAIT1()  asm volatile("cp.async.wait_group 1;\n" ::: "memory")

__device__ __forceinline__ float sigmoid_fast(float x) {
    // fp32 EX2 + RCP, unconditional. Branch-free (R13 lesson: any branch inside the
    // unrolled nb loop wrecks ptxas scheduling). fp32 arg mandatory (R7 lesson).
    return __fdividef(1.0f, 1.0f + __expf(-x));
}

// ---------------- fused projection kernel ----------------
// One pass over X[N,128]: G = relu(X@Wg+Bg) -> fp16 + |g16|^2, and
// H = X@Wh+Bh -> fp16 + fp16 residual (h32 - h16).
__global__ __launch_bounds__(256) void proj_fused_kernel(
    const float* __restrict__ X,
    const float* __restrict__ Wg, const float* __restrict__ Bg,
    const float* __restrict__ Wh, const float* __restrict__ Bh,
    __half* __restrict__ G, float* __restrict__ SQ,
    __half* __restrict__ H, __half* __restrict__ HR)
{
    __shared__ __align__(16) float Xs [32 * 132];
    __shared__ __align__(16) float Wgs[32 * 64];
    __shared__ __align__(16) float Whs[32 * 128];

    const int tid  = threadIdx.x;
    const int lane = tid & 31;
    const int wy   = tid >> 5;
    const int rowbase = blockIdx.x * 32;

    #pragma unroll
    for (int i = tid; i < 32 * 32; i += 256) {
        int r = i >> 5, c = i & 31;
        ((float4*)(Xs + r * 132))[c] =
            ((const float4*)(X + (size_t)(rowbase + r) * 128))[c];
    }

    float accg[4][2], acch[4][4];
    #pragma unroll
    for (int rs = 0; rs < 4; rs++) {
        accg[rs][0] = accg[rs][1] = 0.f;
        #pragma unroll
        for (int cs = 0; cs < 4; cs++) acch[rs][cs] = 0.f;
    }

    for (int kc = 0; kc < 128; kc += 32) {
        __syncthreads();
        #pragma unroll
        for (int i = tid; i < 512; i += 256)
            ((float4*)Wgs)[i] = ((const float4*)(Wg + (size_t)kc * 64))[i];
        #pragma unroll
        for (int i = tid; i < 1024; i += 256)
            ((float4*)Whs)[i] = ((const float4*)(Wh + (size_t)kc * 128))[i];
        __syncthreads();

        #pragma unroll
        for (int k4 = 0; k4 < 8; k4++) {
            float4 xv[4];
            #pragma unroll
            for (int rs = 0; rs < 4; rs++)
                xv[rs] = *(const float4*)(Xs + (wy + rs * 8) * 132 + kc + k4 * 4);
            #pragma unroll
            for (int kk = 0; kk < 4; kk++) {
                const int k = k4 * 4 + kk;
                float2 wg2 = *(const float2*)(Wgs + k * 64 + lane * 2);
                float4 wh4 = *(const float4*)(Whs + k * 128 + lane * 4);
                #pragma unroll
                for (int rs = 0; rs < 4; rs++) {
                    float xk = ((const float*)&xv[rs])[kk];
                    accg[rs][0] = fmaf(xk, wg2.x, accg[rs][0]);
                    accg[rs][1] = fmaf(xk, wg2.y, accg[rs][1]);
                    acch[rs][0] = fmaf(xk, wh4.x, acch[rs][0]);
                    acch[rs][1] = fmaf(xk, wh4.y, acch[rs][1]);
                    acch[rs][2] = fmaf(xk, wh4.z, acch[rs][2]);
                    acch[rs][3] = fmaf(xk, wh4.w, acch[rs][3]);
                }
            }
        }
    }

    #pragma unroll
    for (int rs = 0; rs < 4; rs++) {
        const int row = rowbase + wy + rs * 8;
        // G part: cols lane*2 + {0,1}, relu, fp16, |g16|^2
        float ssq = 0.f;
        #pragma unroll
        for (int cs = 0; cs < 2; cs++) {
            int col = lane * 2 + cs;
            float v = fmaxf(accg[rs][cs] + Bg[col], 0.f);
            __half h = __float2half_rn(v);
            G[(size_t)row * 64 + col] = h;
            float vh = __half2float(h);
            ssq += vh * vh;
        }
        #pragma unroll
        for (int off = 16; off; off >>= 1) ssq += __shfl_xor_sync(0xffffffffu, ssq, off);
        if (lane == 0) SQ[row] = ssq;
        // H part: cols lane*4 + {0..3}, fp16 + residual
        #pragma unroll
        for (int cs = 0; cs < 4; cs++) {
            int col = lane * 4 + cs;
            float v = acch[rs][cs] + Bh[col];
            __half h = __float2half_rn(v);
            H[(size_t)row * 128 + col] = h;
            HR[(size_t)row * 128 + col] = __float2half_rn(v - __half2float(h));
        }
    }
}

// ---------------- fused sigmoid-attention kernel (persistent, key-split) ----------------
// partialO[kc] += sigmoid(t*(2 g_i.g_j - sq_i - sq_j) + th) @ h ; partialRS[kc] += rowsum
// R8 compute exactly (branch-free fp32 sigmoid); 3-stage cp.async, ONE barrier per iter.
// Occupancy 1 (R12 lesson: occ-2 reg cap spills accO).

// dynamic smem (bytes): 3 stages of {K 64x72 f16, H 64x136 f16, SQ 64 f32}
#define OFF_K(b)   ((b) * 9216)
#define OFF_H(b)   (27648 + (b) * 17408)
#define OFF_SQ(b)  (79872 + (b) * 256)
#define SMEM_BYTES 80640

__global__ __launch_bounds__(256, 1) void attn_kernel(
    const __half* __restrict__ G, const float* __restrict__ SQ,
    const __half* __restrict__ H,
    const float* __restrict__ tempp, const float* __restrict__ thetap,
    float* __restrict__ PO, float* __restrict__ PRS)
{
    extern __shared__ __align__(16) char dsm[];
    const uint32_t smem_u32 = (uint32_t)__cvta_generic_to_shared(dsm);

    const int tid  = threadIdx.x;
    const int lane = tid & 31;
    const int warp = tid >> 5;
    const int gid  = lane >> 2;
    const int qid  = lane & 3;

    const float tt = 1.0f + *tempp;       // t
    const float th = 5.0f + *thetap;
    const float t2 = 2.0f * tt;
    const uint32_t ONES = 0x3C003C00u;

    const uint32_t* G32 = reinterpret_cast<const uint32_t*>(G);

    for (int t = blockIdx.x; t < TILES; t += GRID_ATTN) {
        const int rb = t & 127;
        const int kc = t >> 7;
        const int keybase = kc * CHUNK;
        const int rowbase = rb * 128 + warp * 16;
        const int r0 = rowbase + gid, r1 = r0 + 8;

        // Q fragments
        uint32_t aq[4][4];
        #pragma unroll
        for (int ks = 0; ks < 4; ks++) {
            int c0 = ks * 8 + qid;
            aq[ks][0] = G32[(size_t)r0 * 32 + c0];
            aq[ks][1] = G32[(size_t)r1 * 32 + c0];
            aq[ks][2] = G32[(size_t)r0 * 32 + c0 + 4];
            aq[ks][3] = G32[(size_t)r1 * 32 + c0 + 4];
        }
        const float ci0 = fmaf(-tt, SQ[r0], th);   // th - t*sq_i
        const float ci1 = fmaf(-tt, SQ[r1], th);

        float accO[16][4];
        #pragma unroll
        for (int i = 0; i < 16; i++)
            #pragma unroll
            for (int j = 0; j < 4; j++) accO[i][j] = 0.f;
        float rsacc[4] = {0.f, 0.f, 0.f, 0.f};

        // ---- async tile loader (stage b = it % 3) ----
        auto issue = [&](int it2) {
            if (it2 < NIT) {
                const int b = it2 % 3;
                const int j0 = keybase + it2 * 64;
                uint32_t kdst = smem_u32 + OFF_K(b);
                const char* ksrc = (const char*)(G + (size_t)j0 * 64);
                #pragma unroll
                for (int i = tid; i < 512; i += 256) {
                    int r = i >> 3, c = i & 7;
                    cp16(kdst + (r * 72 + c * 8) * 2, ksrc + i * 16);
                }
                uint32_t hdst = smem_u32 + OFF_H(b);
                const char* hsrc = (const char*)(H + (size_t)j0 * 128);
                #pragma unroll
                for (int i = tid; i < 1024; i += 256) {
                    int r = i >> 4, c = i & 15;
                    cp16(hdst + (r * 136 + c * 8) * 2, hsrc + i * 16);
                }
                if (tid < 16)
                    cp16(smem_u32 + OFF_SQ(b) + tid * 16, (const char*)(SQ + j0) + tid * 16);
            }
        };

        issue(0); CP_COMMIT();
        issue(1); CP_COMMIT();

        for (int it = 0; it < NIT; it++) {
            const int b = it % 3;

            CP_WAIT1();          // tile(it) resident (pending groups were: it, it+1)
            __syncthreads();     // all warps done with compute(it-1) -> buf (it-1)%3 reusable
            issue(it + 2);       // writes buf (it+2)%3 == (it-1)%3 : safe after barrier
            CP_COMMIT();

            const uint32_t skb = smem_u32 + OFF_K(b);
            const uint32_t shb = smem_u32 + OFF_H(b);
            const float* sqb = (const float*)(dsm + OFF_SQ(b));

            // ---- S = Gq @ Gk^T -> P = sigmoid (fp32, branch-free) -> fp16 pack ----
            uint32_t pP[8][2];
            #pragma unroll
            for (int nb = 0; nb < 8; nb++) {
                float c4[4] = {0.f, 0.f, 0.f, 0.f};
                uint32_t b0, b1, b2, b3, b4, b5, b6, b7;
                uint32_t addr = skb + ((nb * 8 + (lane & 7)) * 72 + (lane >> 3) * 8) * 2;
                ldsm4(b0, b1, b2, b3, addr);
                ldsm4(b4, b5, b6, b7, addr + 64);
                mma_16816(c4, aq[0], b0, b1);
                mma_16816(c4, aq[1], b2, b3);
                mma_16816(c4, aq[2], b4, b5);
                mma_16816(c4, aq[3], b6, b7);

                float tsq0 = tt * sqb[nb * 8 + qid * 2];
                float tsq1 = tt * sqb[nb * 8 + qid * 2 + 1];
                float p00 = sigmoid_fast(fmaf(t2, c4[0], ci0 - tsq0));
                float p01 = sigmoid_fast(fmaf(t2, c4[1], ci0 - tsq1));
                float p10 = sigmoid_fast(fmaf(t2, c4[2], ci1 - tsq0));
                float p11 = sigmoid_fast(fmaf(t2, c4[3], ci1 - tsq1));

                __half2 ph0 = __floats2half2_rn(p00, p01);
                __half2 ph1 = __floats2half2_rn(p10, p11);
                pP[nb][0] = *reinterpret_cast<uint32_t*>(&ph0);
                pP[nb][1] = *reinterpret_cast<uint32_t*>(&ph1);
            }

            // ---- O += P @ H ; rowsum += P @ 1 (same fp16 P, fp32 accum) ----
            #pragma unroll
            for (int ks = 0; ks < 4; ks++) {
                uint32_t ap[4] = { pP[2*ks][0], pP[2*ks][1], pP[2*ks+1][0], pP[2*ks+1][1] };
                mma_16816(rsacc, ap, ONES, ONES);
                #pragma unroll
                for (int np = 0; np < 8; np++) {
                    uint32_t h0, h1, h2, h3;
                    uint32_t addr = shb +
                        ((ks * 16 + ((lane >> 3) & 1) * 8 + (lane & 7)) * 136 +
                         np * 16 + (lane >> 4) * 8) * 2;
                    ldsm4t(h0, h1, h2, h3, addr);
                    mma_16816(accO[2 * np],     ap, h0, h1);
                    mma_16816(accO[2 * np + 1], ap, h2, h3);
                }
            }
        }

        // ---- store partial O and rowsums ----
        float* po = PO + (size_t)kc * NROWS * 128;
        #pragma unroll
        for (int nb = 0; nb < 16; nb++) {
            int c0 = nb * 8 + qid * 2;
            *(float2*)(po + (size_t)r0 * 128 + c0) = make_float2(accO[nb][0], accO[nb][1]);
            *(float2*)(po + (size_t)r1 * 128 + c0) = make_float2(accO[nb][2], accO[nb][3]);
        }
        if (qid == 0) {
            PRS[(size_t)kc * NROWS + r0] = rsacc[0];
            PRS[(size_t)kc * NROWS + r1] = rsacc[2];
        }
        __syncthreads();   // protect stage buffers from next tile's prologue issues
    }
}

// ---------------- combine: sum partials, diag residual, normalize, relu ----------------
__global__ __launch_bounds__(256) void combine_kernel(
    const float* __restrict__ PO, const float* __restrict__ PRS,
    const __half* __restrict__ HR, const float* __restrict__ thetap,
    float* __restrict__ X, int do_relu)
{
    const int row = blockIdx.x * 2 + (threadIdx.x >> 7);
    const int col = threadIdx.x & 127;
    const float th = 5.0f + *thetap;
    const float pd = 1.0f / (1.0f + expf(-th));

    float acc = 0.f, rs = 0.f;
    #pragma unroll
    for (int k = 0; k < KSPLIT; k++) {
        acc += PO[((size_t)k * NROWS + row) * 128 + col];
        rs  += PRS[(size_t)k * NROWS + row];
    }
    float hr = __half2float(HR[(size_t)row * 128 + col]);
    float v = fmaf(pd, hr, acc) / rs;
    if (do_relu) v = fmaxf(v, 0.f);
    X[(size_t)row * 128 + col] = v;
}

// ---------------- final projection (128->10) + softmax ----------------
__global__ __launch_bounds__(256) void out_kernel(
    const float* __restrict__ X, const float* __restrict__ W,
    const float* __restrict__ B, float* __restrict__ out)
{
    int gw = (blockIdx.x * blockDim.x + threadIdx.x) >> 5;
    int lane = threadIdx.x & 31;
    if (gw >= NROWS) return;
    const float* x = X + (size_t)gw * 128;
    float xv0 = x[lane], xv1 = x[lane + 32], xv2 = x[lane + 64], xv3 = x[lane + 96];
    float lg[10];
    #pragma unroll
    for (int c = 0; c < 10; c++) {
        float s = xv0 * W[lane * 10 + c] + xv1 * W[(lane + 32) * 10 + c]
                + xv2 * W[(lane + 64) * 10 + c] + xv3 * W[(lane + 96) * 10 + c];
        #pragma unroll
        for (int off = 16; off; off >>= 1) s += __shfl_xor_sync(0xffffffffu, s, off);
        lg[c] = s + B[c];
    }
    if (lane == 0) {
        float mx = lg[0];
        #pragma unroll
        for (int c = 1; c < 10; c++) mx = fmaxf(mx, lg[c]);
        float den = 0.f, e[10];
        #pragma unroll
        for (int c = 0; c < 10; c++) { e[c] = expf(lg[c] - mx); den += e[c]; }
        float inv = 1.0f / den;
        #pragma unroll
        for (int c = 0; c < 10; c++) out[(size_t)gw * 10 + c] = e[c] * inv;
    }
}

// ---------------- launch ----------------
extern "C" void kernel_launch(void* const* d_in, const int* in_sizes, int n_in,
                              void* d_out, int out_size)
{
    const float* feat   = (const float*)d_in[0];
    const float* gl_w0  = (const float*)d_in[1];
    const float* gl_b0  = (const float*)d_in[2];
    const float* gl_w1  = (const float*)d_in[3];
    const float* gl_b1  = (const float*)d_in[4];
    const float* gnn_w0 = (const float*)d_in[5];
    const float* gnn_b0 = (const float*)d_in[6];
    const float* gnn_w1 = (const float*)d_in[7];
    const float* gnn_b1 = (const float*)d_in[8];
    const float* out_w  = (const float*)d_in[9];
    const float* out_b  = (const float*)d_in[10];
    const float* temp   = (const float*)d_in[11];
    const float* theta  = (const float*)d_in[12];

    float*  Xp;  cudaGetSymbolAddress((void**)&Xp,  g_X);
    __half* Gp;  cudaGetSymbolAddress((void**)&Gp,  g_G);
    float*  SQp; cudaGetSymbolAddress((void**)&SQp, g_SQ);
    __half* Hp;  cudaGetSymbolAddress((void**)&Hp,  g_H);
    __half* HRp; cudaGetSymbolAddress((void**)&HRp, g_HR);
    float*  POp; cudaGetSymbolAddress((void**)&POp, g_PO);
    float*  PRSp;cudaGetSymbolAddress((void**)&PRSp,g_PRS);

    static bool attr_set = false;
    if (!attr_set) {
        cudaFuncSetAttribute(attn_kernel, cudaFuncAttributeMaxDynamicSharedMemorySize,
                             SMEM_BYTES);
        attr_set = true;
    }

    // layer 1
    proj_fused_kernel<<<NROWS / 32, 256>>>(feat, gl_w0, gl_b0, gnn_w0, gnn_b0,
                                           Gp, SQp, Hp, HRp);
    attn_kernel<<<GRID_ATTN, 256, SMEM_BYTES>>>(Gp, SQp, Hp, temp, theta, POp, PRSp);
    combine_kernel<<<NROWS / 2, 256>>>(POp, PRSp, HRp, theta, Xp, 1);

    // layer 2
    proj_fused_kernel<<<NROWS / 32, 256>>>(Xp, gl_w1, gl_b1, gnn_w1, gnn_b1,
                                           Gp, SQp, Hp, HRp);
    attn_kernel<<<GRID_ATTN, 256, SMEM_BYTES>>>(Gp, SQp, Hp, temp, theta, POp, PRSp);
    combine_kernel<<<NROWS / 2, 256>>>(POp, PRSp, HRp, theta, Xp, 0);

    // output head + softmax
    out_kernel<<<NROWS * 32 / 256, 256>>>(Xp, out_w, out_b, (float*)d_out);
}